// round 17
// baseline (speedup 1.0000x reference)
#include <cuda_runtime.h>

#define NB      4
#define P       8192
#define NPTS    (NB * P)            // 32768
#define NBIN1   64
#define NBINS   (NBIN1 * NBIN1)     // 4096 per batch
#define GBINS   (NB * NBINS)        // 16384
#define XMIN    (-5.0f)
#define BINW    0.15625f            // 10 / 64
#define INVW    6.4f
#define NEG_INF (-3.402823466e38f)

#define SCAN_TPB 1024
#define BPT      (GBINS / SCAN_TPB) // 16 bins per scan-thread
#define CAP      2880               // SMEM point capacity (46080 B)
#define SRCH_TPB 256
#define SRCH_BLK (NB * NBIN1 * 2)   // 512: (batch, row, half)
#define FB_BLK   512
#define FB_TPB   256
#define FB_WARPS (FB_BLK * FB_TPB / 32)  // 4096

__device__ int    d_tcnt[GBINS], d_scnt[GBINS];
__device__ int    d_toff[GBINS], d_soff[GBINS];
__device__ int    d_tcur[GBINS], d_scur[GBINS];
__device__ float4 d_tp[NPTS];       // sorted targets: (x, y, z, -0.5*|t|^2)
__device__ float4 d_sp[NPTS];       // sorted sources: (x, y, z, bitcast(orig idx))
__device__ float  g_nn[NPTS];       // nn_d2 by ORIGINAL source index
__device__ int    d_fb[NPTS];       // deferred source slots
__device__ int    d_fbcnt;          // zero-init; re-zeroed by k_sum

__device__ __forceinline__ int clampi(int v, int lo, int hi) {
    return v < lo ? lo : (v > hi ? hi : v);
}
__device__ __forceinline__ int bin2d(float x, float y) {
    int bx = clampi((int)((x - XMIN) * INVW), 0, NBIN1 - 1);
    int by = clampi((int)((y - XMIN) * INVW), 0, NBIN1 - 1);
    return by * NBIN1 + bx;
}
__device__ __forceinline__ float warp_max(float v) {
    #pragma unroll
    for (int o = 16; o; o >>= 1)
        v = fmaxf(v, __shfl_xor_sync(0xffffffffu, v, o));
    return v;
}

// ---------------- K1: histogram ----------------
__global__ void k_count(const float* __restrict__ src, const float* __restrict__ tgt) {
    int i = blockIdx.x * blockDim.x + threadIdx.x;   // 0..2*NPTS-1
    if (i < NPTS) {
        const float* t = tgt + (long)i * 3;
        int b = i / P;
        atomicAdd(&d_tcnt[b * NBINS + bin2d(t[0], t[1])], 1);
    } else {
        int j = i - NPTS;
        const float* s = src + (long)j * 3;
        int b = j / P;
        atomicAdd(&d_scnt[b * NBINS + bin2d(s[0], s[1])], 1);
    }
}

// ---------------- K2: shuffle-scan alloc ----------------
__global__ __launch_bounds__(SCAN_TPB) void k_alloc() {
    __shared__ int warp_tot[32];
    const int tid  = threadIdx.x;
    const int lane = tid & 31, wid = tid >> 5;
    const bool is_t = (blockIdx.x == 0);
    const int* cnt = is_t ? d_tcnt : d_scnt;

    int local[BPT];
    int sum = 0;
    const int b0 = tid * BPT;
    #pragma unroll
    for (int j = 0; j < BPT; j++) { local[j] = cnt[b0 + j]; sum += local[j]; }

    int inc = sum;
    #pragma unroll
    for (int d = 1; d < 32; d <<= 1) {
        int v = __shfl_up_sync(0xffffffffu, inc, d);
        if (lane >= d) inc += v;
    }
    if (lane == 31) warp_tot[wid] = inc;
    __syncthreads();
    if (wid == 0) {
        int v = warp_tot[lane];
        int iv = v;
        #pragma unroll
        for (int d = 1; d < 32; d <<= 1) {
            int u = __shfl_up_sync(0xffffffffu, iv, d);
            if (lane >= d) iv += u;
        }
        warp_tot[lane] = iv - v;
    }
    __syncthreads();

    int base = warp_tot[wid] + (inc - sum);
    #pragma unroll
    for (int j = 0; j < BPT; j++) {
        int g = b0 + j;
        if (is_t) { d_toff[g] = base; d_tcur[g] = base; }
        else      { d_soff[g] = base; d_scur[g] = base; }
        base += local[j];
    }
}

// ---------------- K3: scatter ----------------
__global__ void k_scatter(const float* __restrict__ src, const float* __restrict__ tgt) {
    int i = blockIdx.x * blockDim.x + threadIdx.x;
    if (i < NPTS) {
        const float* t = tgt + (long)i * 3;
        float x = t[0], y = t[1], z = t[2];
        int b = i / P;
        int g = b * NBINS + bin2d(x, y);
        int pos = atomicAdd(&d_tcur[g], 1);
        d_tp[pos] = make_float4(x, y, z, -0.5f * (x * x + y * y + z * z));
    } else {
        int j = i - NPTS;
        const float* s = src + (long)j * 3;
        float x = s[0], y = s[1], z = s[2];
        int b = j / P;
        int g = b * NBINS + bin2d(x, y);
        int pos = atomicAdd(&d_scur[g], 1);
        d_sp[pos] = make_float4(x, y, z, __int_as_float(j));
    }
}

// ---------------- K4: pass A — SMEM window, THREAD-per-source, defer hard cases ----------------
__global__ __launch_bounds__(SRCH_TPB) void k_search() {
    __shared__ float4 pts[CAP];      // 3 target bin-rows
    __shared__ int2   bt[3 * NBIN1]; // (off, cnt) for rows rlo..rhi

    const int tid   = threadIdx.x;
    const int batch = blockIdx.x >> 7;
    const int rem   = blockIdx.x & 127;
    const int row   = rem >> 1;
    const int half  = rem & 1;
    const int tbase = batch * NBINS;
    const int sbase = batch * NBINS;

    const int gs0 = sbase + row * NBIN1;
    const int gs1 = gs0 + NBIN1 - 1;
    const int srow0 = d_soff[gs0];
    const int srow1 = d_soff[gs1] + d_scnt[gs1];
    const int nsrc  = srow1 - srow0;
    if (nsrc == 0) return;
    const int cnt0  = (nsrc + 1) >> 1;
    const int s0    = half ? (srow0 + cnt0) : srow0;
    const int s1    = half ? srow1 : (srow0 + cnt0);
    if (s0 >= s1) return;

    const int rlo = clampi(row - 1, 0, NBIN1 - 1);
    const int rhi = clampi(row + 1, 0, NBIN1 - 1);
    const int gt0 = tbase + rlo * NBIN1;
    const int gt1 = tbase + rhi * NBIN1 + NBIN1 - 1;
    const int t0  = d_toff[gt0];
    const int n   = d_toff[gt1] + d_tcnt[gt1] - t0;
    const bool overflow = (n > CAP);   // never expected; safe: all sources deferred

    for (int i = tid; i < 3 * NBIN1; i += SRCH_TPB) {
        int rr = clampi(rlo + i / NBIN1, 0, NBIN1 - 1);
        int g  = tbase + rr * NBIN1 + (i & (NBIN1 - 1));
        bt[i] = make_int2(d_toff[g], d_tcnt[g]);
    }
    if (!overflow)
        for (int i = tid; i < n; i += SRCH_TPB) pts[i] = d_tp[t0 + i];
    __syncthreads();

    // ---- one source per THREAD; independent chains, SMEM broadcast across warp ----
    for (int s = s0 + tid; s < s1; s += SRCH_TPB) {
        float4 S = d_sp[s];
        const float sx = S.x, sy = S.y, sz = S.z;
        const int   idx = __float_as_int(S.w);
        const float s2 = sx * sx + sy * sy + sz * sz;
        const int   bx = clampi((int)((sx - XMIN) * INVW), 0, NBIN1 - 1);
        const int   x0 = clampi(bx - 1, 0, NBIN1 - 1);
        const int   x1 = clampi(bx + 1, 0, NBIN1 - 1);

        float m = NEG_INF;
        if (!overflow) {
            #pragma unroll
            for (int rr = 0; rr < 3; rr++) {
                int r = rlo + rr;
                if (r > rhi) break;
                int2 b0 = bt[rr * NBIN1 + x0];
                int2 b1 = bt[rr * NBIN1 + x1];
                int ke = b1.x + b1.y - t0;
                for (int k = b0.x - t0; k < ke; k++) {
                    float4 t = pts[k];
                    m = fmaxf(m, fmaf(sx, t.x, fmaf(sy, t.y, fmaf(sz, t.z, t.w))));
                }
            }
        }
        float d2 = fmaxf(0.0f, fmaf(-2.0f, m, s2));
        // proven exact iff NN strictly inside radius-1 window:
        // any unscanned bin (Chebyshev >= 2) holds points >= 1*BINW away
        if (m != NEG_INF && d2 < BINW * BINW) {
            g_nn[idx] = d2;
        } else {
            int pos = atomicAdd(&d_fbcnt, 1);
            d_fb[pos] = s;
        }
    }
}

// ---------------- K5: pass B — warp-per-source global square scan (exact) ----------------
#define WSCANSQ(R) do {                                                         \
    int _y0 = clampi(row - (R), 0, NBIN1 - 1);                                  \
    int _y1 = clampi(row + (R), 0, NBIN1 - 1);                                  \
    int _x0 = clampi(bx - (R), 0, NBIN1 - 1);                                   \
    int _x1 = clampi(bx + (R), 0, NBIN1 - 1);                                   \
    for (int _y = _y0; _y <= _y1; _y++) {                                       \
        int _g0 = tbase + _y * NBIN1 + _x0;                                     \
        int _g1 = tbase + _y * NBIN1 + _x1;                                     \
        int _e  = d_toff[_g1] + d_tcnt[_g1];                                    \
        for (int _k = d_toff[_g0] + lane; _k < _e; _k += 32) {                  \
            float4 _t = d_tp[_k];                                               \
            m = fmaxf(m, fmaf(sx, _t.x, fmaf(sy, _t.y, fmaf(sz, _t.z, _t.w)))); \
        }                                                                       \
    }                                                                           \
} while (0)

__global__ __launch_bounds__(FB_TPB) void k_fallback() {
    const int lane = threadIdx.x & 31;
    const int w    = blockIdx.x * (FB_TPB / 32) + (threadIdx.x >> 5);
    const int cnt  = d_fbcnt;

    for (int i = w; i < cnt; i += FB_WARPS) {
        const int s = d_fb[i];
        float4 S = d_sp[s];
        const float sx = S.x, sy = S.y, sz = S.z;
        const int   idx = __float_as_int(S.w);
        const float s2 = sx * sx + sy * sy + sz * sz;
        const int batch = s / P;                  // slots are batch-major
        const int tbase = batch * NBINS;
        const int bx  = clampi((int)((sx - XMIN) * INVW), 0, NBIN1 - 1);
        const int row = clampi((int)((sy - XMIN) * INVW), 0, NBIN1 - 1);

        float m = NEG_INF;
        WSCANSQ(1);
        float mm = warp_max(m);
        int Rdone = 1;
        while (mm == NEG_INF && Rdone < NBIN1) {
            Rdone *= 2;
            WSCANSQ(Rdone);
            mm = warp_max(m);
        }
        float d2 = fmaxf(0.0f, fmaf(-2.0f, mm, s2));
        int Rneed = (int)(sqrtf(d2) * INVW) + 1;  // conservative ceil
        if (Rneed > Rdone) {
            WSCANSQ(Rneed);                        // superset rescan; max idempotent
            mm = warp_max(m);
            d2 = fmaxf(0.0f, fmaf(-2.0f, mm, s2));
        }
        if (lane == 0) g_nn[idx] = d2;
    }
}
#undef WSCANSQ

// ---------------- K6: deterministic fixed-order sum + re-zero state ----------------
__global__ __launch_bounds__(1024) void k_sum(float* __restrict__ out) {
    __shared__ float red[1024];
    const int tid = threadIdx.x;
    float acc = 0.0f;
    #pragma unroll
    for (int c = 0; c < NPTS / 1024; c++)         // fixed ascending order
        acc += g_nn[c * 1024 + tid];
    red[tid] = acc;
    __syncthreads();
    #pragma unroll
    for (int st = 512; st > 0; st >>= 1) {
        if (tid < st) red[tid] += red[tid + st];
        __syncthreads();
    }
    if (tid == 0) { out[0] = red[0] * (1.0f / (float)NB); d_fbcnt = 0; }

    #pragma unroll
    for (int c = 0; c < GBINS / 1024; c++) {
        d_tcnt[c * 1024 + tid] = 0;
        d_scnt[c * 1024 + tid] = 0;
    }
}

extern "C" void kernel_launch(void* const* d_in, const int* in_sizes, int n_in,
                              void* d_out, int out_size) {
    const float* src = (const float*)d_in[0];   // (4, 8192, 3) f32
    const float* tgt = (const float*)d_in[1];   // (4, 8192, 3) f32
    float* out = (float*)d_out;                  // scalar f32

    k_count   <<<(2 * NPTS) / 256, 256>>>(src, tgt);
    k_alloc   <<<2, SCAN_TPB>>>();
    k_scatter <<<(2 * NPTS) / 256, 256>>>(src, tgt);
    k_search  <<<SRCH_BLK, SRCH_TPB>>>();
    k_fallback<<<FB_BLK, FB_TPB>>>();
    k_sum     <<<1, 1024>>>(out);
}